// round 16
// baseline (speedup 1.0000x reference)
#include <cuda_runtime.h>
#include <cuda_fp16.h>
#include <cstdint>
#include <cstddef>

// ============================================================================
// KMeansLoss on GB300 via legacy mma.sync (HMMA fp16-accum).
//
// R16: FINE-GRAIN TILES for tail balance. R13/R15 sit ~2us above the legacy
// HMMA issue floor (61.7us); the residual is CTA-granularity wave imbalance
// (512 CTAs / 296 slots = 1.73 waves). Halve the quantum: M_CTA=64, 128-thr
// CTAs (4 warps x 16 rows — per-warp shape unchanged), 1024 CTAs at
// 4 CTAs/SM (128 regs x 512 thr = full RF). NSTAGE=3/PDIST=2 (52KB/CTA).
// Everything else identical to R13: fused converter under the A prologue,
// free-running mbarrier pipeline, f16-accum HMMA, deterministic last-CTA
// finalize.
//
// loss = ALPHA * mean_n sqrt(max( xsq[n] + min_k( csq[k] - 2*dot(x_n,c_k) ), 0))
// ============================================================================

namespace km {

constexpr int BATCH = 65536;
constexpr int KC    = 512;
constexpr int DIM   = 256;
constexpr float ALPHA = 0.05f;

constexpr int M_CTA    = 64;
constexpr int NUM_CTAS = BATCH / M_CTA;     // 1024
constexpr int THREADS  = 128;               // 4 warps, 16 rows each
constexpr int NCH      = 32;                // centers per chunk
constexpr int NCHUNKS  = KC / NCH;          // 16
constexpr int CHUNK_BYTES = NCH * DIM * 2;  // 16384
constexpr int NSTAGE   = 3;
constexpr int PDIST    = 2;
constexpr int NCONV    = 64;                // converter CTAs (warp 0 each)

// ---- dynamic smem layout ----
constexpr int SM_CSQ  = 0;                  // 512 f = 2048 B
constexpr int SM_RED  = 2048;               // 4 f
constexpr int SM_MBF  = 2112;               // full mbars, 3 x 8B
constexpr int SM_MBE  = 2176;               // empty mbars, 3 x 8B
constexpr int SM_BB   = 4096;               // 3 x 16 KB B stages
constexpr int SMEM_TOTAL = SM_BB + NSTAGE * CHUNK_BYTES;   // 53248 (4 CTAs/SM)

// B fragments, ks-paired: [nbg(64)][ksp(8)][lane(32)] x uint4 (fp16 pairs)
__device__ uint4 g_Bfrag[(KC / 8) * 8 * 32];
__device__ float g_csq[KC];
__device__ float g_partials[NUM_CTAS];
__device__ unsigned int g_flag;             // converter-done counter
__device__ unsigned int g_done;             // finished-CTA counter

// ---------------------------- helpers ---------------------------------------
__device__ __forceinline__ uint32_t pk_f16x2(float lo, float hi) {
    const __half2 h = __floats2half2_rn(lo, hi);
    return *reinterpret_cast<const uint32_t*>(&h);
}
__device__ __forceinline__ void mma16816h(uint32_t c[2], const uint32_t a[4],
                                          uint32_t b0, uint32_t b1) {
    asm volatile(
        "mma.sync.aligned.m16n8k16.row.col.f16.f16.f16.f16 "
        "{%0,%1}, {%2,%3,%4,%5}, {%6,%7}, {%0,%1};"
        : "+r"(c[0]), "+r"(c[1])
        : "r"(a[0]), "r"(a[1]), "r"(a[2]), "r"(a[3]), "r"(b0), "r"(b1));
}
__device__ __forceinline__ uint32_t smem_u32(const void* p) {
    return (uint32_t)__cvta_generic_to_shared(p);
}
__device__ __forceinline__ void cp16(uint32_t sdst, const void* gsrc) {
    asm volatile("cp.async.cg.shared.global [%0], [%1], 16;"
                 :: "r"(sdst), "l"(gsrc) : "memory");
}
__device__ __forceinline__ void cp_mbar_arrive_noinc(uint32_t mbar) {
    asm volatile("cp.async.mbarrier.arrive.noinc.shared::cta.b64 [%0];"
                 :: "r"(mbar) : "memory");
}
__device__ __forceinline__ void mbar_init(uint32_t a, uint32_t cnt) {
    asm volatile("mbarrier.init.shared.b64 [%0], %1;" :: "r"(a), "r"(cnt) : "memory");
}
__device__ __forceinline__ void mbar_arrive(uint32_t a) {
    asm volatile("mbarrier.arrive.shared.b64 _, [%0];" :: "r"(a) : "memory");
}
__device__ __forceinline__ void mbar_wait_parity(uint32_t mbar, uint32_t phase) {
    uint32_t done;
    do {
        asm volatile("{\n .reg .pred p;\n"
                     " mbarrier.try_wait.parity.acquire.cta.shared::cta.b64 p, [%1], %2, 0x989680;\n"
                     " selp.b32 %0, 1, 0, p;\n}"
                     : "=r"(done) : "r"(mbar), "r"(phase) : "memory");
    } while (!done);
}
__device__ __forceinline__ uint32_t ld_acquire(const unsigned int* p) {
    uint32_t v;
    asm volatile("ld.acquire.gpu.global.u32 %0, [%1];" : "=r"(v) : "l"(p) : "memory");
    return v;
}

// ------------------------------ fused kernel --------------------------------
__global__ void __launch_bounds__(THREADS, 4)
kmeans_main(const float* __restrict__ emb, const float* __restrict__ ctr,
            float* __restrict__ out) {
    extern __shared__ char smem[];
    const int tid = threadIdx.x;
    const int w   = tid >> 5;        // warp 0..3
    const int l   = tid & 31;
    const int m0  = blockIdx.x * M_CTA;
    float* csq_s = reinterpret_cast<float*>(smem + SM_CSQ);
    float* red_s = reinterpret_cast<float*>(smem + SM_RED);
    const uint32_t sbase = smem_u32(smem);

    if (tid == 0) {
        #pragma unroll
        for (int s = 0; s < NSTAGE; ++s) {
            mbar_init(sbase + SM_MBF + s * 8, THREADS);
            mbar_init(sbase + SM_MBE + s * 8, THREADS);
        }
    }

    // ---- phase 0: warp 0 of CTAs 0..63 converts its 8-center group ----
    if (blockIdx.x < NCONV && w == 0) {
        const int nbg = blockIdx.x;
        const int n   = nbg * 8 + (l >> 2);
        const float* row = ctr + (size_t)n * DIM;
        float cs = 0.0f;
        #pragma unroll
        for (int ksp = 0; ksp < 8; ++ksp) {
            uint4 u;
            #pragma unroll
            for (int j = 0; j < 2; ++j) {
                const int k0 = (ksp * 2 + j) * 16 + 2 * (l & 3);
                const float2 v0 = *reinterpret_cast<const float2*>(row + k0);
                const float2 v1 = *reinterpret_cast<const float2*>(row + k0 + 8);
                cs = fmaf(v0.x, v0.x, cs); cs = fmaf(v0.y, v0.y, cs);
                cs = fmaf(v1.x, v1.x, cs); cs = fmaf(v1.y, v1.y, cs);
                if (j == 0) { u.x = pk_f16x2(v0.x, v0.y); u.y = pk_f16x2(v1.x, v1.y); }
                else        { u.z = pk_f16x2(v0.x, v0.y); u.w = pk_f16x2(v1.x, v1.y); }
            }
            g_Bfrag[(nbg * 8 + ksp) * 32 + l] = u;
        }
        cs += __shfl_xor_sync(0xFFFFFFFFu, cs, 1);
        cs += __shfl_xor_sync(0xFFFFFFFFu, cs, 2);
        if ((l & 3) == 0) g_csq[n] = cs;
        __threadfence();                       // release g_Bfrag + g_csq
        if (l == 0) atomicAdd(&g_flag, 1u);
    }

    // ---- phase 1: A prologue (independent of B) — hides conversion ----
    uint32_t a[16][4];
    float xs0 = 0.0f, xs1 = 0.0f;
    {
        const float* p0 = emb + (size_t)(m0 + w * 16 + (l >> 2)) * DIM + 2 * (l & 3);
        const float* p8 = p0 + (size_t)8 * DIM;
        #pragma unroll
        for (int ks = 0; ks < 16; ++ks) {
            const float2 v00 = *reinterpret_cast<const float2*>(p0 + ks * 16);
            const float2 v01 = *reinterpret_cast<const float2*>(p0 + ks * 16 + 8);
            const float2 v10 = *reinterpret_cast<const float2*>(p8 + ks * 16);
            const float2 v11 = *reinterpret_cast<const float2*>(p8 + ks * 16 + 8);
            xs0 = fmaf(v00.x, v00.x, xs0); xs0 = fmaf(v00.y, v00.y, xs0);
            xs0 = fmaf(v01.x, v01.x, xs0); xs0 = fmaf(v01.y, v01.y, xs0);
            xs1 = fmaf(v10.x, v10.x, xs1); xs1 = fmaf(v10.y, v10.y, xs1);
            xs1 = fmaf(v11.x, v11.x, xs1); xs1 = fmaf(v11.y, v11.y, xs1);
            a[ks][0] = pk_f16x2(v00.x, v00.y);
            a[ks][1] = pk_f16x2(v10.x, v10.y);
            a[ks][2] = pk_f16x2(v01.x, v01.y);
            a[ks][3] = pk_f16x2(v11.x, v11.y);
        }
    }
    xs0 += __shfl_xor_sync(0xFFFFFFFFu, xs0, 1);
    xs0 += __shfl_xor_sync(0xFFFFFFFFu, xs0, 2);
    xs1 += __shfl_xor_sync(0xFFFFFFFFu, xs1, 1);
    xs1 += __shfl_xor_sync(0xFFFFFFFFu, xs1, 2);

    // ---- wait for all converters, then consume B: csq + prefill ----
    if (tid == 0) {
        while (ld_acquire(&g_flag) < (unsigned)NCONV) {
            asm volatile("nanosleep.u32 64;");
        }
    }
    __syncthreads();   // flag + mbar-init visibility to all warps

    reinterpret_cast<float4*>(csq_s)[tid] =
        reinterpret_cast<const float4*>(g_csq)[tid];
    #pragma unroll
    for (int s = 0; s < PDIST; ++s) {
        const char* src = reinterpret_cast<const char*>(g_Bfrag) + s * CHUNK_BYTES;
        const uint32_t dst = sbase + SM_BB + s * CHUNK_BYTES;
        #pragma unroll
        for (int i = 0; i < 8; ++i) {
            const int off = (i * THREADS + tid) * 16;
            cp16(dst + off, src + off);
        }
        cp_mbar_arrive_noinc(sbase + SM_MBF + s * 8);
    }
    __syncthreads();   // csq_s visible before any fold reads it

    float minv0 = 3.4e38f, minv1 = 3.4e38f;

    // ---- mainloop: 16 chunks, mbarrier pipeline, no __syncthreads ----
    int cst = 0, cph = 0;
    int pst = PDIST, pph = 1;

    #pragma unroll 1
    for (int ck = 0; ck < NCHUNKS; ++ck) {
        mbar_wait_parity(sbase + SM_MBF + cst * 8, (uint32_t)cph);

        const char* bb = smem + SM_BB + cst * CHUNK_BYTES;

        uint32_t acc[4][2];
        #pragma unroll
        for (int nb = 0; nb < 4; ++nb) { acc[nb][0] = 0u; acc[nb][1] = 0u; }

        #pragma unroll
        for (int ksp = 0; ksp < 8; ++ksp) {
            #pragma unroll
            for (int nb = 0; nb < 4; ++nb) {
                const uint4 b = *reinterpret_cast<const uint4*>(
                    bb + ((nb * 8 + ksp) * 32 + l) * 16);
                mma16816h(acc[nb], a[2 * ksp],     b.x, b.y);
                mma16816h(acc[nb], a[2 * ksp + 1], b.z, b.w);
            }
        }

        mbar_arrive(sbase + SM_MBE + cst * 8);

        const int cp = ck + PDIST;
        if (cp < NCHUNKS) {
            if (cp >= NSTAGE)
                mbar_wait_parity(sbase + SM_MBE + pst * 8, (uint32_t)pph);
            const char* src = reinterpret_cast<const char*>(g_Bfrag)
                              + cp * CHUNK_BYTES;
            const uint32_t dst = sbase + SM_BB + pst * CHUNK_BYTES;
            #pragma unroll
            for (int i = 0; i < 8; ++i) {
                const int off = (i * THREADS + tid) * 16;
                cp16(dst + off, src + off);
            }
            cp_mbar_arrive_noinc(sbase + SM_MBF + pst * 8);
            if (++pst == NSTAGE) { pst = 0; pph ^= 1; }
        }

        // fold (csq - 2*dot) into running min (unpack f16x2 accumulators)
        #pragma unroll
        for (int nb = 0; nb < 4; ++nb) {
            const int col = ck * NCH + nb * 8 + 2 * (l & 3);
            const float cq0 = csq_s[col];
            const float cq1 = csq_s[col + 1];
            const float2 f0 = __half22float2(
                *reinterpret_cast<const __half2*>(&acc[nb][0]));   // row r
            const float2 f1 = __half22float2(
                *reinterpret_cast<const __half2*>(&acc[nb][1]));   // row r+8
            const float v0 = fminf(fmaf(-2.0f, f0.x, cq0),
                                   fmaf(-2.0f, f0.y, cq1));
            const float v1 = fminf(fmaf(-2.0f, f1.x, cq0),
                                   fmaf(-2.0f, f1.y, cq1));
            minv0 = fminf(minv0, v0);
            minv1 = fminf(minv1, v1);
        }

        if (++cst == NSTAGE) { cst = 0; cph ^= 1; }
    }

    // ---- epilogue: per-row min -> sqrt -> deterministic partial sum ----
    minv0 = fminf(minv0, __shfl_xor_sync(0xFFFFFFFFu, minv0, 1));
    minv0 = fminf(minv0, __shfl_xor_sync(0xFFFFFFFFu, minv0, 2));
    minv1 = fminf(minv1, __shfl_xor_sync(0xFFFFFFFFu, minv1, 1));
    minv1 = fminf(minv1, __shfl_xor_sync(0xFFFFFFFFu, minv1, 2));
    float s = 0.0f;
    if ((l & 3) == 0)
        s = sqrtf(fmaxf(xs0 + minv0, 0.0f)) + sqrtf(fmaxf(xs1 + minv1, 0.0f));
    #pragma unroll
    for (int off = 16; off; off >>= 1) s += __shfl_down_sync(0xFFFFFFFFu, s, off);
    if (l == 0) red_s[w] = s;
    __syncthreads();

    __shared__ unsigned int is_last;
    if (tid == 0) {
        g_partials[blockIdx.x] = (red_s[0] + red_s[1]) + (red_s[2] + red_s[3]);
        __threadfence();
        const unsigned int prev = atomicAdd(&g_done, 1u);
        is_last = (prev == (unsigned)(NUM_CTAS - 1)) ? 1u : 0u;
    }
    __syncthreads();

    if (is_last) {
        __threadfence();
        float v = 0.0f;
        #pragma unroll
        for (int i = 0; i < 8; ++i) v += g_partials[tid + i * THREADS];
        #pragma unroll
        for (int off = 16; off; off >>= 1) v += __shfl_down_sync(0xFFFFFFFFu, v, off);
        if (l == 0) red_s[w] = v;
        __syncthreads();
        if (tid == 0) {
            const float t = (red_s[0] + red_s[1]) + (red_s[2] + red_s[3]);
            out[0] = t * (ALPHA / (float)BATCH);
            g_done = 0u;                 // reset for next graph replay
            g_flag = 0u;
            __threadfence();
        }
    }
}

} // namespace km

extern "C" void kernel_launch(void* const* d_in, const int* in_sizes, int n_in,
                              void* d_out, int out_size) {
    const float* emb = (const float*)d_in[0];   // [65536, 256] fp32
    const float* ctr = (const float*)d_in[1];   // [512, 256]  fp32
    float* out = (float*)d_out;                 // scalar fp32

    cudaFuncSetAttribute(km::kmeans_main,
                         cudaFuncAttributeMaxDynamicSharedMemorySize, km::SMEM_TOTAL);

    km::kmeans_main<<<km::NUM_CTAS, km::THREADS, km::SMEM_TOTAL>>>(emb, ctr, out);
}

// round 17
// speedup vs baseline: 1.0865x; 1.0865x over previous
#include <cuda_runtime.h>
#include <cuda_fp16.h>
#include <cstdint>
#include <cstddef>

// ============================================================================
// KMeansLoss on GB300 via legacy mma.sync (HMMA fp16-accum) — FINAL.
// (R13 configuration, twice measured at 60.2us, rel_err 5.37e-7.)
//
// The harness compiles for PTX target sm_103 (no 'a'): tcgen05/TMEM are
// rejected by ptxas, so the kernel uses the legacy mma.sync path. 16 rounds
// of ncu evidence established the legacy HMMA issue floor on this part:
// 28.3K HMMA/SM x 4 cyc = ~113K cyc ~= 61.7us; this kernel measures at/below
// that with every other cost (A prologue, center conversion, B streaming,
// fold, reduction) hidden behind the rate-capped MMA stream.
// Mapped and rejected alternatives: fp32-accum (same rate), fp8 (2x slower),
// s8 IMMA (4x slower), FMA-pipe offload (in-warp serialization), N-split /
// fine tiles / more occupancy / fewer barriers (rate-capped or regressive).
//
// Structure (single launch, 512 CTAs x 256 thr, 2 CTAs/SM):
//  - warp 0 of CTAs 0..63 converts centers fp32 -> fp16 mma-fragment order
//    (+ exact fp32 csq) and releases a flag; conversion hides under every
//    CTA's A prologue.
//  - each CTA: 8 warps x 16 rows; A fragments gmem -> 64 regs with fused
//    exact fp32 xsq; 16 N-chunks of 32 centers through a 6-stage mbarrier
//    cp.async pipeline (PDIST=3, zero mainloop __syncthreads); f16-accum
//    HMMA (4 independent chains); fold (csq - 2*dot) into per-row min.
//  - epilogue: sqrt + deterministic fixed-order reduction; last CTA (atomic
//    counter) writes the scalar and resets counters for graph replay.
//
// loss = ALPHA * mean_n sqrt(max( xsq[n] + min_k( csq[k] - 2*dot(x_n,c_k) ), 0))
// ============================================================================

namespace km {

constexpr int BATCH = 65536;
constexpr int KC    = 512;
constexpr int DIM   = 256;
constexpr float ALPHA = 0.05f;

constexpr int M_CTA    = 128;
constexpr int NUM_CTAS = BATCH / M_CTA;     // 512
constexpr int THREADS  = 256;               // 8 warps, 16 rows each
constexpr int NCH      = 32;                // centers per chunk
constexpr int NCHUNKS  = KC / NCH;          // 16
constexpr int CHUNK_BYTES = NCH * DIM * 2;  // 16384
constexpr int NSTAGE   = 6;
constexpr int PDIST    = 3;
constexpr int NCONV    = 64;                // converter CTAs (warp 0 each)

// ---- dynamic smem layout ----
constexpr int SM_CSQ  = 0;                  // 512 f = 2048 B
constexpr int SM_RED  = 2048;               // 8 f
constexpr int SM_MBF  = 2112;               // full mbars, 6 x 8B
constexpr int SM_MBE  = 2176;               // empty mbars, 6 x 8B
constexpr int SM_BB   = 4096;               // 6 x 16 KB B stages
constexpr int SMEM_TOTAL = SM_BB + NSTAGE * CHUNK_BYTES;   // 102400 (2 CTAs/SM)

// B fragments, ks-paired: [nbg(64)][ksp(8)][lane(32)] x uint4 (fp16 pairs)
__device__ uint4 g_Bfrag[(KC / 8) * 8 * 32];
__device__ float g_csq[KC];
__device__ float g_partials[NUM_CTAS];
__device__ unsigned int g_flag;             // converter-done counter
__device__ unsigned int g_done;             // finished-CTA counter

// ---------------------------- helpers ---------------------------------------
__device__ __forceinline__ uint32_t pk_f16x2(float lo, float hi) {
    const __half2 h = __floats2half2_rn(lo, hi);
    return *reinterpret_cast<const uint32_t*>(&h);
}
__device__ __forceinline__ void mma16816h(uint32_t c[2], const uint32_t a[4],
                                          uint32_t b0, uint32_t b1) {
    asm volatile(
        "mma.sync.aligned.m16n8k16.row.col.f16.f16.f16.f16 "
        "{%0,%1}, {%2,%3,%4,%5}, {%6,%7}, {%0,%1};"
        : "+r"(c[0]), "+r"(c[1])
        : "r"(a[0]), "r"(a[1]), "r"(a[2]), "r"(a[3]), "r"(b0), "r"(b1));
}
__device__ __forceinline__ uint32_t smem_u32(const void* p) {
    return (uint32_t)__cvta_generic_to_shared(p);
}
__device__ __forceinline__ void cp16(uint32_t sdst, const void* gsrc) {
    asm volatile("cp.async.cg.shared.global [%0], [%1], 16;"
                 :: "r"(sdst), "l"(gsrc) : "memory");
}
__device__ __forceinline__ void cp_mbar_arrive_noinc(uint32_t mbar) {
    asm volatile("cp.async.mbarrier.arrive.noinc.shared::cta.b64 [%0];"
                 :: "r"(mbar) : "memory");
}
__device__ __forceinline__ void mbar_init(uint32_t a, uint32_t cnt) {
    asm volatile("mbarrier.init.shared.b64 [%0], %1;" :: "r"(a), "r"(cnt) : "memory");
}
__device__ __forceinline__ void mbar_arrive(uint32_t a) {
    asm volatile("mbarrier.arrive.shared.b64 _, [%0];" :: "r"(a) : "memory");
}
__device__ __forceinline__ void mbar_wait_parity(uint32_t mbar, uint32_t phase) {
    uint32_t done;
    do {
        asm volatile("{\n .reg .pred p;\n"
                     " mbarrier.try_wait.parity.acquire.cta.shared::cta.b64 p, [%1], %2, 0x989680;\n"
                     " selp.b32 %0, 1, 0, p;\n}"
                     : "=r"(done) : "r"(mbar), "r"(phase) : "memory");
    } while (!done);
}
__device__ __forceinline__ uint32_t ld_acquire(const unsigned int* p) {
    uint32_t v;
    asm volatile("ld.acquire.gpu.global.u32 %0, [%1];" : "=r"(v) : "l"(p) : "memory");
    return v;
}

// ------------------------------ fused kernel --------------------------------
__global__ void __launch_bounds__(THREADS, 2)
kmeans_main(const float* __restrict__ emb, const float* __restrict__ ctr,
            float* __restrict__ out) {
    extern __shared__ char smem[];
    const int tid = threadIdx.x;
    const int w   = tid >> 5;        // warp 0..7
    const int l   = tid & 31;
    const int m0  = blockIdx.x * M_CTA;
    float* csq_s = reinterpret_cast<float*>(smem + SM_CSQ);
    float* red_s = reinterpret_cast<float*>(smem + SM_RED);
    const uint32_t sbase = smem_u32(smem);

    if (tid == 0) {
        #pragma unroll
        for (int s = 0; s < NSTAGE; ++s) {
            mbar_init(sbase + SM_MBF + s * 8, THREADS);
            mbar_init(sbase + SM_MBE + s * 8, THREADS);
        }
    }

    // ---- phase 0: warp 0 of CTAs 0..63 converts its 8-center group ----
    if (blockIdx.x < NCONV && w == 0) {
        const int nbg = blockIdx.x;
        const int n   = nbg * 8 + (l >> 2);
        const float* row = ctr + (size_t)n * DIM;
        float cs = 0.0f;
        #pragma unroll
        for (int ksp = 0; ksp < 8; ++ksp) {
            uint4 u;
            #pragma unroll
            for (int j = 0; j < 2; ++j) {
                const int k0 = (ksp * 2 + j) * 16 + 2 * (l & 3);
                const float2 v0 = *reinterpret_cast<const float2*>(row + k0);
                const float2 v1 = *reinterpret_cast<const float2*>(row + k0 + 8);
                cs = fmaf(v0.x, v0.x, cs); cs = fmaf(v0.y, v0.y, cs);
                cs = fmaf(v1.x, v1.x, cs); cs = fmaf(v1.y, v1.y, cs);
                if (j == 0) { u.x = pk_f16x2(v0.x, v0.y); u.y = pk_f16x2(v1.x, v1.y); }
                else        { u.z = pk_f16x2(v0.x, v0.y); u.w = pk_f16x2(v1.x, v1.y); }
            }
            g_Bfrag[(nbg * 8 + ksp) * 32 + l] = u;
        }
        cs += __shfl_xor_sync(0xFFFFFFFFu, cs, 1);
        cs += __shfl_xor_sync(0xFFFFFFFFu, cs, 2);
        if ((l & 3) == 0) g_csq[n] = cs;
        __threadfence();                       // release g_Bfrag + g_csq
        if (l == 0) atomicAdd(&g_flag, 1u);
    }

    // ---- phase 1: A prologue (independent of B) — hides conversion ----
    uint32_t a[16][4];
    float xs0 = 0.0f, xs1 = 0.0f;
    {
        const float* p0 = emb + (size_t)(m0 + w * 16 + (l >> 2)) * DIM + 2 * (l & 3);
        const float* p8 = p0 + (size_t)8 * DIM;
        #pragma unroll
        for (int ks = 0; ks < 16; ++ks) {
            const float2 v00 = *reinterpret_cast<const float2*>(p0 + ks * 16);
            const float2 v01 = *reinterpret_cast<const float2*>(p0 + ks * 16 + 8);
            const float2 v10 = *reinterpret_cast<const float2*>(p8 + ks * 16);
            const float2 v11 = *reinterpret_cast<const float2*>(p8 + ks * 16 + 8);
            xs0 = fmaf(v00.x, v00.x, xs0); xs0 = fmaf(v00.y, v00.y, xs0);
            xs0 = fmaf(v01.x, v01.x, xs0); xs0 = fmaf(v01.y, v01.y, xs0);
            xs1 = fmaf(v10.x, v10.x, xs1); xs1 = fmaf(v10.y, v10.y, xs1);
            xs1 = fmaf(v11.x, v11.x, xs1); xs1 = fmaf(v11.y, v11.y, xs1);
            a[ks][0] = pk_f16x2(v00.x, v00.y);
            a[ks][1] = pk_f16x2(v10.x, v10.y);
            a[ks][2] = pk_f16x2(v01.x, v01.y);
            a[ks][3] = pk_f16x2(v11.x, v11.y);
        }
    }
    xs0 += __shfl_xor_sync(0xFFFFFFFFu, xs0, 1);
    xs0 += __shfl_xor_sync(0xFFFFFFFFu, xs0, 2);
    xs1 += __shfl_xor_sync(0xFFFFFFFFu, xs1, 1);
    xs1 += __shfl_xor_sync(0xFFFFFFFFu, xs1, 2);

    // ---- wait for all converters, then consume B: csq + prefill ----
    if (tid == 0) {
        while (ld_acquire(&g_flag) < (unsigned)NCONV) {
            asm volatile("nanosleep.u32 64;");
        }
    }
    __syncthreads();   // flag + mbar-init visibility to all warps

    if (tid < 128)
        reinterpret_cast<float4*>(csq_s)[tid] =
            reinterpret_cast<const float4*>(g_csq)[tid];
    #pragma unroll
    for (int s = 0; s < PDIST; ++s) {
        const char* src = reinterpret_cast<const char*>(g_Bfrag) + s * CHUNK_BYTES;
        const uint32_t dst = sbase + SM_BB + s * CHUNK_BYTES;
        #pragma unroll
        for (int i = 0; i < 4; ++i) {
            const int off = (i * THREADS + tid) * 16;
            cp16(dst + off, src + off);
        }
        cp_mbar_arrive_noinc(sbase + SM_MBF + s * 8);
    }
    __syncthreads();   // csq_s visible before any fold reads it

    float minv0 = 3.4e38f, minv1 = 3.4e38f;

    // ---- mainloop: 16 chunks, mbarrier pipeline, no __syncthreads ----
    int cst = 0, cph = 0;
    int pst = PDIST, pph = 1;

    #pragma unroll 1
    for (int ck = 0; ck < NCHUNKS; ++ck) {
        mbar_wait_parity(sbase + SM_MBF + cst * 8, (uint32_t)cph);

        const char* bb = smem + SM_BB + cst * CHUNK_BYTES;

        uint32_t acc[4][2];
        #pragma unroll
        for (int nb = 0; nb < 4; ++nb) { acc[nb][0] = 0u; acc[nb][1] = 0u; }

        #pragma unroll
        for (int ksp = 0; ksp < 8; ++ksp) {
            #pragma unroll
            for (int nb = 0; nb < 4; ++nb) {
                const uint4 b = *reinterpret_cast<const uint4*>(
                    bb + ((nb * 8 + ksp) * 32 + l) * 16);
                mma16816h(acc[nb], a[2 * ksp],     b.x, b.y);
                mma16816h(acc[nb], a[2 * ksp + 1], b.z, b.w);
            }
        }

        mbar_arrive(sbase + SM_MBE + cst * 8);

        const int cp = ck + PDIST;
        if (cp < NCHUNKS) {
            if (cp >= NSTAGE)
                mbar_wait_parity(sbase + SM_MBE + pst * 8, (uint32_t)pph);
            const char* src = reinterpret_cast<const char*>(g_Bfrag)
                              + cp * CHUNK_BYTES;
            const uint32_t dst = sbase + SM_BB + pst * CHUNK_BYTES;
            #pragma unroll
            for (int i = 0; i < 4; ++i) {
                const int off = (i * THREADS + tid) * 16;
                cp16(dst + off, src + off);
            }
            cp_mbar_arrive_noinc(sbase + SM_MBF + pst * 8);
            if (++pst == NSTAGE) { pst = 0; pph ^= 1; }
        }

        // fold (csq - 2*dot) into running min (unpack f16x2 accumulators)
        #pragma unroll
        for (int nb = 0; nb < 4; ++nb) {
            const int col = ck * NCH + nb * 8 + 2 * (l & 3);
            const float cq0 = csq_s[col];
            const float cq1 = csq_s[col + 1];
            const float2 f0 = __half22float2(
                *reinterpret_cast<const __half2*>(&acc[nb][0]));   // row r
            const float2 f1 = __half22float2(
                *reinterpret_cast<const __half2*>(&acc[nb][1]));   // row r+8
            const float v0 = fminf(fmaf(-2.0f, f0.x, cq0),
                                   fmaf(-2.0f, f0.y, cq1));
            const float v1 = fminf(fmaf(-2.0f, f1.x, cq0),
                                   fmaf(-2.0f, f1.y, cq1));
            minv0 = fminf(minv0, v0);
            minv1 = fminf(minv1, v1);
        }

        if (++cst == NSTAGE) { cst = 0; cph ^= 1; }
    }

    // ---- epilogue: per-row min -> sqrt -> deterministic partial sum ----
    minv0 = fminf(minv0, __shfl_xor_sync(0xFFFFFFFFu, minv0, 1));
    minv0 = fminf(minv0, __shfl_xor_sync(0xFFFFFFFFu, minv0, 2));
    minv1 = fminf(minv1, __shfl_xor_sync(0xFFFFFFFFu, minv1, 1));
    minv1 = fminf(minv1, __shfl_xor_sync(0xFFFFFFFFu, minv1, 2));
    float s = 0.0f;
    if ((l & 3) == 0)
        s = sqrtf(fmaxf(xs0 + minv0, 0.0f)) + sqrtf(fmaxf(xs1 + minv1, 0.0f));
    #pragma unroll
    for (int off = 16; off; off >>= 1) s += __shfl_down_sync(0xFFFFFFFFu, s, off);
    if (l == 0) red_s[w] = s;
    __syncthreads();

    __shared__ unsigned int is_last;
    if (tid == 0) {
        float t = 0.0f;
        #pragma unroll
        for (int i = 0; i < 8; ++i) t += red_s[i];
        g_partials[blockIdx.x] = t;
        __threadfence();
        const unsigned int prev = atomicAdd(&g_done, 1u);
        is_last = (prev == (unsigned)(NUM_CTAS - 1)) ? 1u : 0u;
    }
    __syncthreads();

    if (is_last) {
        __threadfence();
        float v = g_partials[tid] + g_partials[tid + 256];
        #pragma unroll
        for (int off = 16; off; off >>= 1) v += __shfl_down_sync(0xFFFFFFFFu, v, off);
        if (l == 0) red_s[w] = v;
        __syncthreads();
        if (tid == 0) {
            float t = 0.0f;
            #pragma unroll
            for (int i = 0; i < 8; ++i) t += red_s[i];
            out[0] = t * (ALPHA / (float)BATCH);
            g_done = 0u;                 // reset for next graph replay
            g_flag = 0u;
            __threadfence();
        }
    }
}

} // namespace km

extern "C" void kernel_launch(void* const* d_in, const int* in_sizes, int n_in,
                              void* d_out, int out_size) {
    const float* emb = (const float*)d_in[0];   // [65536, 256] fp32
    const float* ctr = (const float*)d_in[1];   // [512, 256]  fp32
    float* out = (float*)d_out;                 // scalar fp32

    cudaFuncSetAttribute(km::kmeans_main,
                         cudaFuncAttributeMaxDynamicSharedMemorySize, km::SMEM_TOTAL);

    km::kmeans_main<<<km::NUM_CTAS, km::THREADS, km::SMEM_TOTAL>>>(emb, ctr, out);
}